// round 10
// baseline (speedup 1.0000x reference)
#include <cuda_runtime.h>
#include <cuda_fp16.h>
#include <stdint.h>
#include <math.h>

#define B_SZ    32
#define T_STEPS 128
#define I_CH    16
#define N_DIM   512

// ---------------- scratch ----------------
// W image (fp16): 128 blobs (i*8+kt) x 256KB; blob = 8 chunks (64 n) x 32KB.
// addr(c,ks,pp) per warp: blob + kc*4096 + lane*16 + c*32768 + pp*2048 + ks*512
// unit = {b0(col_a),b1(col_a),b0(col_b),b1(col_b)}, col_a = kc*32+pp*16+gid, col_b = col_a+8.
__device__ __align__(128) uint8_t g_wimg[128 * 262144];
__device__ unsigned int g_bar[16 * 32];   // per-channel barrier, 128B apart

struct Params {
    const float* x;
    const float* U[4];
    const float* W[4];
    const float* bias[4];
    float* out;
};

// ---------------- helpers ----------------
__device__ __forceinline__ void mma16816(float* d, uint32_t a0, uint32_t a1, uint32_t a2,
                                         uint32_t a3, uint32_t b0, uint32_t b1) {
    asm volatile(
        "mma.sync.aligned.m16n8k16.row.col.f32.f16.f16.f32 "
        "{%0,%1,%2,%3}, {%4,%5,%6,%7}, {%8,%9}, {%0,%1,%2,%3};"
        : "+f"(d[0]), "+f"(d[1]), "+f"(d[2]), "+f"(d[3])
        : "r"(a0), "r"(a1), "r"(a2), "r"(a3), "r"(b0), "r"(b1));
}
__device__ __forceinline__ uint32_t packh(float x, float y) {
    __half hx = __float2half_rn(x), hy = __float2half_rn(y);
    return (uint32_t)__half_as_ushort(hx) | ((uint32_t)__half_as_ushort(hy) << 16);
}
__device__ __forceinline__ float fsigmoid(float x) {
    return 1.0f / (1.0f + __expf(-x));
}
__device__ __forceinline__ float ftanh(float x) {
    return 2.0f / (1.0f + __expf(-2.0f * x)) - 1.0f;
}

// ---------------- prep: transpose + fp16-pack W; reset barriers ----------------
__global__ __launch_bounds__(256) void prep_kernel(Params p) {
    __shared__ float ts[128 * 68];     // [n 128][ko 64 + pad]
    int blob = blockIdx.x;             // 0..127
    int i = blob >> 3, kt = blob & 7;
    if (kt == 0 && threadIdx.x == 0) g_bar[i * 32] = 0;
    int m0 = kt * 64;
    uint8_t* dst = g_wimg + (size_t)blob * 262144;
    int tid = threadIdx.x;

    for (int g = 0; g < 4; ++g) {
        const float* W = p.W[g] + (size_t)i * N_DIM * N_DIM;
        for (int nb = 0; nb < 4; ++nb) {            // 128-n groups
            __syncthreads();
            #pragma unroll
            for (int o = 0; o < 8; ++o) {
                int e = o * 256 + tid;              // 2048 float4 = 128 n x 16
                int row = e >> 4, q = e & 15;
                float4 v = *reinterpret_cast<const float4*>(
                    W + (size_t)(nb * 128 + row) * N_DIM + m0 + q * 4);
                float* sp = ts + row * 68 + q * 4;
                sp[0] = v.x; sp[1] = v.y; sp[2] = v.z; sp[3] = v.w;
            }
            __syncthreads();
            #pragma unroll
            for (int o = 0; o < 4; ++o) {
                int idx = o * 256 + tid;            // 1024 units per (g, nb)
                int cl  = idx >> 9;                 // local chunk (64 n each)
                int r   = idx & 511;
                int kcl = (r >> 8) & 1, pp = (r >> 7) & 1;
                int ks  = (r >> 5) & 3, lane = r & 31;
                int gid = lane >> 2, tig = lane & 3;
                int ko_a = kcl * 32 + pp * 16 + gid;
                int ko_b = ko_a + 8;
                int n0 = cl * 64 + ks * 16 + tig * 2;
                uint4 u;
                u.x = packh(ts[n0 * 68 + ko_a],       ts[(n0 + 1) * 68 + ko_a]);
                u.y = packh(ts[(n0 + 8) * 68 + ko_a], ts[(n0 + 9) * 68 + ko_a]);
                u.z = packh(ts[n0 * 68 + ko_b],       ts[(n0 + 1) * 68 + ko_b]);
                u.w = packh(ts[(n0 + 8) * 68 + ko_b], ts[(n0 + 9) * 68 + ko_b]);
                int kc = 2 * g + kcl;
                int chunk = nb * 2 + cl;
                *reinterpret_cast<uint4*>(
                    dst + (size_t)chunk * 32768
                        + ((((kc * 2 + pp) * 4 + ks) * 32 + lane) << 4)) = u;
            }
        }
    }
}

// ---------------- persistent kernel ----------------
// dyn SMEM: A_hi @0 (32K) | A_lo @32768 | h32 @65536 (8K) | x_s @73728 (16K)
// s_pre overlays @0 (A dead by then). A unit (16B) at (((c*4+ks)*2+bh)*32 + lane)*16
#define SM_A_LO 32768
#define SM_H32  65536
#define SM_XS   73728
#define SM_TOT  90112

__global__ __launch_bounds__(512, 1) void persist_kernel(Params p) {
    const int kt = blockIdx.x;   // 0..7 (64-wide k_out tile)
    const int i  = blockIdx.y;   // 0..15
    extern __shared__ __align__(16) uint8_t sm[];
    const uint8_t* blob = g_wimg + (size_t)(i * 8 + kt) * 262144;
    const int tid = threadIdx.x;

    const int lane = tid & 31, w = tid >> 5;
    const int bh = w & 1, kc = w >> 1;          // kc 0..7
    const int gid = lane >> 2, tig = lane & 3;

    // per-warp B base: addr(c,ks,pp) = wp + c*32768 + pp*2048 + ks*512
    const uint8_t* wp = blob + kc * 4096 + lane * 16;

    // epilogue ownership
    const int ko = tid & 63;
    const int kg = kt * 64 + ko;
    const int eb0 = tid >> 6;                   // 0..7
    const float uj = p.U[0][i * N_DIM + kg], ui = p.U[1][i * N_DIM + kg];
    const float uf = p.U[2][i * N_DIM + kg], uo = p.U[3][i * N_DIM + kg];
    const float bj = p.bias[0][i * N_DIM + kg], bi2 = p.bias[1][i * N_DIM + kg];
    const float bf2 = p.bias[2][i * N_DIM + kg], bo2 = p.bias[3][i * N_DIM + kg];
    float creg[4] = {0.f, 0.f, 0.f, 0.f};

    float* h32   = reinterpret_cast<float*>(sm + SM_H32);
    float* x_s   = reinterpret_cast<float*>(sm + SM_XS);    // [32][128]
    float* s_pre = reinterpret_cast<float*>(sm);            // [32][260] overlays A

    unsigned int* bar = &g_bar[i * 32];

    // preload x for this channel: x_s[b][t]
    #pragma unroll
    for (int o = 0; o < 8; ++o) {
        int e = o * 512 + tid;                  // 4096 = 32 b x 128 t
        int b = e >> 7, tt = e & 127;
        x_s[e] = p.x[((size_t)b * T_STEPS + tt) * I_CH + i];
    }

    for (int t = 0; t < T_STEPS; ++t) {
        // ---- stage A (h split fp16) ----
        if (t == 0) {
            #pragma unroll
            for (int o = 0; o < 9; ++o)         // A(4096 uint4) + h32(512 uint4)
                reinterpret_cast<uint4*>(sm)[o * 512 + tid] = make_uint4(0, 0, 0, 0);
        } else {
            #pragma unroll
            for (int o = 0; o < 16; ++o) {
                int pr = o * 512 + tid;           // 8192 pairs: b(32) x P(256)
                int b = pr >> 8, P = pr & 255;
                float2 v = __ldcg(reinterpret_cast<const float2*>(
                    p.out + (((size_t)b * T_STEPS + (t - 1)) * I_CH + i) * N_DIM + P * 2));
                __half h0 = __float2half_rn(v.x), h1 = __float2half_rn(v.y);
                uint32_t hv = (uint32_t)__half_as_ushort(h0) |
                              ((uint32_t)__half_as_ushort(h1) << 16);
                uint32_t lv = packh(v.x - __half2float(h0), v.y - __half2float(h1));
                int c = P >> 5;
                int ks = (P >> 3) & 3, half = (P >> 2) & 1, tg = P & 3;
                int bhh = b >> 4, rr = b & 15, gg = rr & 7, top = rr >> 3;
                uint32_t a16 = (uint32_t)((((c * 4 + ks) * 2 + bhh) * 32 + gg * 4 + tg) * 16
                                          + (half * 2 + top) * 4);
                *reinterpret_cast<uint32_t*>(sm + a16)           = hv;
                *reinterpret_cast<uint32_t*>(sm + SM_A_LO + a16) = lv;
            }
        }
        __syncthreads();

        // ---- mainloop: 32 flat (c,ks) iterations, B via LDG, 1-ahead prefetch ----
        float d[4][4];
        #pragma unroll
        for (int a = 0; a < 4; ++a)
            #pragma unroll
            for (int b = 0; b < 4; ++b) d[a][b] = 0.0f;

        uint4 Bn0 = __ldg(reinterpret_cast<const uint4*>(wp));
        uint4 Bn1 = __ldg(reinterpret_cast<const uint4*>(wp + 2048));

        #pragma unroll 4
        for (int it = 0; it < 32; ++it) {
            const int c = it >> 2, ks = it & 3;
            uint4 B0 = Bn0, B1 = Bn1;
            if (it + 1 < 32) {
                const int it2 = it + 1;
                const uint8_t* q = wp + (it2 >> 2) * 32768 + (it2 & 3) * 512;
                Bn0 = __ldg(reinterpret_cast<const uint4*>(q));
                Bn1 = __ldg(reinterpret_cast<const uint4*>(q + 2048));
            }
            uint32_t ab = (uint32_t)((((c * 4 + ks) * 2 + bh) * 32 + lane) * 16);
            uint4 Ah = *reinterpret_cast<const uint4*>(sm + ab);
            uint4 Al = *reinterpret_cast<const uint4*>(sm + SM_A_LO + ab);
            mma16816(d[0], Ah.x, Ah.y, Ah.z, Ah.w, B0.x, B0.y);
            mma16816(d[0], Al.x, Al.y, Al.z, Al.w, B0.x, B0.y);
            mma16816(d[1], Ah.x, Ah.y, Ah.z, Ah.w, B0.z, B0.w);
            mma16816(d[1], Al.x, Al.y, Al.z, Al.w, B0.z, B0.w);
            mma16816(d[2], Ah.x, Ah.y, Ah.z, Ah.w, B1.x, B1.y);
            mma16816(d[2], Al.x, Al.y, Al.z, Al.w, B1.x, B1.y);
            mma16816(d[3], Ah.x, Ah.y, Ah.z, Ah.w, B1.z, B1.w);
            mma16816(d[3], Al.x, Al.y, Al.z, Al.w, B1.z, B1.w);
        }
        __syncthreads();   // A reads done before s_pre overlays A

        // exchange preacts: d[nt] -> col = kc*32 + nt*8
        #pragma unroll
        for (int nt = 0; nt < 4; ++nt) {
            int col = kc * 32 + nt * 8 + tig * 2;
            int b = bh * 16 + gid;
            *reinterpret_cast<float2*>(s_pre + b * 260 + col)       = make_float2(d[nt][0], d[nt][1]);
            *reinterpret_cast<float2*>(s_pre + (b + 8) * 260 + col) = make_float2(d[nt][2], d[nt][3]);
        }
        __syncthreads();

        // ---- fused pointwise epilogue ----
        const float DT = 0.01f;
        const float A_OUT = 0.9900498337491681f;
        const float OMA_OUT = 0.009950166250831947f;
        #pragma unroll
        for (int o = 0; o < 4; ++o) {
            int b = eb0 + o * 8;
            float xb = x_s[b * 128 + t];
            float pj = s_pre[b * 260 +       ko] + xb * uj + bj;
            float pi = s_pre[b * 260 +  64 + ko] + xb * ui + bi2;
            float pf = s_pre[b * 260 + 128 + ko] + xb * uf + bf2;
            float po = s_pre[b * 260 + 192 + ko] + xb * uo + bo2;

            float j  = ftanh(pj);
            float ig = fsigmoid(pi);
            float fg = fsigmoid(pf);
            float og = fsigmoid(po);

            float h_old = h32[b * 64 + ko];

            float xm = -7.8125e-5f * j;
            float alpha_m = 1.0f + xm + 0.5f * xm * xm;
            float xr = -1.5625e-4f * ig;
            float ro = 1.0f + xr + 0.5f * xr * xr;
            float b_ad = ro * 0.1f + (1.0f - ro) * ig;
            float Bth  = 0.04f + 1.8f * b_ad;
            float mem  = j * alpha_m + (1.0f - alpha_m) * h_old - Bth * ig * DT;
            float spike = (mem - Bth) > 0.0f ? 1.0f : 0.0f;
            float mem_out = mem * A_OUT + OMA_OUT * spike + 0.08f;

            float c_new = creg[o] * fg + ig * spike * mem_out;
            creg[o] = c_new;
            float h_new = og * ftanh(c_new);
            h32[b * 64 + ko] = h_new;                       // own slice, own slot
            p.out[(((size_t)b * T_STEPS + t) * I_CH + i) * N_DIM + kg] = h_new;
            if (t == T_STEPS - 1) {
                float* h_fin = p.out + (size_t)B_SZ * T_STEPS * I_CH * N_DIM;
                float* c_fin = h_fin + B_SZ * I_CH * N_DIM;
                size_t fidx = ((size_t)b * I_CH + i) * N_DIM + kg;
                h_fin[fidx] = h_new;
                c_fin[fidx] = c_new;
            }
        }

        // ---- per-channel barrier (8 CTAs of channel i) ----
        if (t + 1 < T_STEPS) {
            __threadfence();
            __syncthreads();
            if (tid == 0) {
                atomicAdd(bar, 1u);
                unsigned target = (unsigned)(t + 1) * 8u;
                unsigned v;
                do {
                    asm volatile("ld.acquire.gpu.u32 %0, [%1];"
                                 : "=r"(v) : "l"(bar) : "memory");
                } while (v < target);
            }
            __syncthreads();
        }
    }
}

extern "C" void kernel_launch(void* const* d_in, const int* in_sizes, int n_in,
                              void* d_out, int out_size) {
    Params p;
    p.x = (const float*)d_in[0];
    for (int g = 0; g < 4; ++g) {
        p.U[g]    = (const float*)d_in[1 + g];
        p.W[g]    = (const float*)d_in[5 + g];
        p.bias[g] = (const float*)d_in[9 + g];
    }
    p.out = (float*)d_out;

    cudaFuncSetAttribute(persist_kernel, cudaFuncAttributeMaxDynamicSharedMemorySize, SM_TOT);

    prep_kernel<<<128, 256>>>(p);                 // also resets barriers each replay
    dim3 grid(8, I_CH);                           // 128 blocks, all co-resident
    persist_kernel<<<grid, 512, SM_TOT>>>(p);
}

// round 11
// speedup vs baseline: 1.0158x; 1.0158x over previous
#include <cuda_runtime.h>
#include <cuda_fp16.h>
#include <stdint.h>
#include <math.h>

#define B_SZ    32
#define T_STEPS 128
#define I_CH    16
#define N_DIM   512

// ---------------- scratch ----------------
// W image (fp16): 128 blobs (i*8+kt) x 256KB; blob = 8 chunks (64 n) x 32KB.
// addr(c,ks,pp) per warp: blob + kc*4096 + lane*16 + c*32768 + pp*2048 + ks*512
// unit = {b0(col_a),b1(col_a),b0(col_b),b1(col_b)}, col_a = kc*32+pp*16+gid, col_b = col_a+8.
__device__ __align__(128) uint8_t g_wimg[128 * 262144];
__device__ unsigned int g_bar[16 * 32];   // per-channel barrier, 128B apart

struct Params {
    const float* x;
    const float* U[4];
    const float* W[4];
    const float* bias[4];
    float* out;
};

// ---------------- helpers ----------------
__device__ __forceinline__ void mma16816(float* d, uint32_t a0, uint32_t a1, uint32_t a2,
                                         uint32_t a3, uint32_t b0, uint32_t b1) {
    asm volatile(
        "mma.sync.aligned.m16n8k16.row.col.f32.f16.f16.f32 "
        "{%0,%1,%2,%3}, {%4,%5,%6,%7}, {%8,%9}, {%0,%1,%2,%3};"
        : "+f"(d[0]), "+f"(d[1]), "+f"(d[2]), "+f"(d[3])
        : "r"(a0), "r"(a1), "r"(a2), "r"(a3), "r"(b0), "r"(b1));
}
__device__ __forceinline__ uint32_t packh(float x, float y) {
    __half hx = __float2half_rn(x), hy = __float2half_rn(y);
    return (uint32_t)__half_as_ushort(hx) | ((uint32_t)__half_as_ushort(hy) << 16);
}

// ---------------- prep: transpose + fp16-pack W; reset barriers ----------------
__global__ __launch_bounds__(256) void prep_kernel(Params p) {
    __shared__ float ts[128 * 68];     // [n 128][ko 64 + pad]
    int blob = blockIdx.x;             // 0..127
    int i = blob >> 3, kt = blob & 7;
    if (kt == 0 && threadIdx.x == 0) g_bar[i * 32] = 0;
    int m0 = kt * 64;
    uint8_t* dst = g_wimg + (size_t)blob * 262144;
    int tid = threadIdx.x;

    for (int g = 0; g < 4; ++g) {
        const float* W = p.W[g] + (size_t)i * N_DIM * N_DIM;
        for (int nb = 0; nb < 4; ++nb) {            // 128-n groups
            __syncthreads();
            #pragma unroll
            for (int o = 0; o < 8; ++o) {
                int e = o * 256 + tid;              // 2048 float4 = 128 n x 16
                int row = e >> 4, q = e & 15;
                float4 v = *reinterpret_cast<const float4*>(
                    W + (size_t)(nb * 128 + row) * N_DIM + m0 + q * 4);
                float* sp = ts + row * 68 + q * 4;
                sp[0] = v.x; sp[1] = v.y; sp[2] = v.z; sp[3] = v.w;
            }
            __syncthreads();
            #pragma unroll
            for (int o = 0; o < 4; ++o) {
                int idx = o * 256 + tid;            // 1024 units per (g, nb)
                int cl  = idx >> 9;                 // local chunk (64 n each)
                int r   = idx & 511;
                int kcl = (r >> 8) & 1, pp = (r >> 7) & 1;
                int ks  = (r >> 5) & 3, lane = r & 31;
                int gid = lane >> 2, tig = lane & 3;
                int ko_a = kcl * 32 + pp * 16 + gid;
                int ko_b = ko_a + 8;
                int n0 = cl * 64 + ks * 16 + tig * 2;
                uint4 u;
                u.x = packh(ts[n0 * 68 + ko_a],       ts[(n0 + 1) * 68 + ko_a]);
                u.y = packh(ts[(n0 + 8) * 68 + ko_a], ts[(n0 + 9) * 68 + ko_a]);
                u.z = packh(ts[n0 * 68 + ko_b],       ts[(n0 + 1) * 68 + ko_b]);
                u.w = packh(ts[(n0 + 8) * 68 + ko_b], ts[(n0 + 9) * 68 + ko_b]);
                int kc = 2 * g + kcl;
                int chunk = nb * 2 + cl;
                *reinterpret_cast<uint4*>(
                    dst + (size_t)chunk * 32768
                        + ((((kc * 2 + pp) * 4 + ks) * 32 + lane) << 4)) = u;
            }
        }
    }
}

// ---------------- persistent kernel ----------------
// dyn SMEM: A_hi @0 (32K) | A_lo @32768 | h32 @65536 (8K) | x_s @73728 (16K) | s_pre @90112 (33280)
// A unit (16B) at (((c*4+ks)*2+bh)*32 + lane)*16
#define SM_A_LO 32768
#define SM_H32  65536
#define SM_XS   73728
#define SM_PRE  90112
#define SM_TOT  123392

__global__ __launch_bounds__(512, 1) void persist_kernel(Params p) {
    const int kt = blockIdx.x;   // 0..7 (64-wide k_out tile)
    const int i  = blockIdx.y;   // 0..15
    extern __shared__ __align__(16) uint8_t sm[];
    const uint8_t* blob = g_wimg + (size_t)(i * 8 + kt) * 262144;
    const int tid = threadIdx.x;

    const int lane = tid & 31, w = tid >> 5;
    const int bh = w & 1, kc = w >> 1;          // kc 0..7
    const int gid = lane >> 2, tig = lane & 3;

    // per-warp B base: addr(c,ks,pp) = wp + c*32768 + pp*2048 + ks*512
    const uint8_t* wp = blob + kc * 4096 + lane * 16;

    // epilogue ownership
    const int ko = tid & 63;
    const int kg = kt * 64 + ko;
    const int eb0 = tid >> 6;                   // 0..7
    const float uj = p.U[0][i * N_DIM + kg], ui = p.U[1][i * N_DIM + kg];
    const float uf = p.U[2][i * N_DIM + kg], uo = p.U[3][i * N_DIM + kg];
    const float bj = p.bias[0][i * N_DIM + kg], bi2 = p.bias[1][i * N_DIM + kg];
    const float bf2 = p.bias[2][i * N_DIM + kg], bo2 = p.bias[3][i * N_DIM + kg];
    float creg[4] = {0.f, 0.f, 0.f, 0.f};

    float* h32   = reinterpret_cast<float*>(sm + SM_H32);
    float* x_s   = reinterpret_cast<float*>(sm + SM_XS);    // [32][128]
    float* s_pre = reinterpret_cast<float*>(sm + SM_PRE);   // [32][260]

    unsigned int* bar = &g_bar[i * 32];

    // preload x for this channel: x_s[b][t]
    #pragma unroll
    for (int o = 0; o < 8; ++o) {
        int e = o * 512 + tid;                  // 4096 = 32 b x 128 t
        int b = e >> 7, tt = e & 127;
        x_s[e] = p.x[((size_t)b * T_STEPS + tt) * I_CH + i];
    }

    for (int t = 0; t < T_STEPS; ++t) {
        // ---- stage A (h split fp16) ----
        if (t == 0) {
            #pragma unroll
            for (int o = 0; o < 9; ++o)         // A(4096 uint4) + h32(512 uint4)
                reinterpret_cast<uint4*>(sm)[o * 512 + tid] = make_uint4(0, 0, 0, 0);
        } else {
            #pragma unroll
            for (int o = 0; o < 16; ++o) {
                int pr = o * 512 + tid;           // 8192 pairs: b(32) x P(256)
                int b = pr >> 8, P = pr & 255;
                float2 v = __ldcg(reinterpret_cast<const float2*>(
                    p.out + (((size_t)b * T_STEPS + (t - 1)) * I_CH + i) * N_DIM + P * 2));
                __half h0 = __float2half_rn(v.x), h1 = __float2half_rn(v.y);
                uint32_t hv = (uint32_t)__half_as_ushort(h0) |
                              ((uint32_t)__half_as_ushort(h1) << 16);
                uint32_t lv = packh(v.x - __half2float(h0), v.y - __half2float(h1));
                int c = P >> 5;
                int ks = (P >> 3) & 3, half = (P >> 2) & 1, tg = P & 3;
                int bhh = b >> 4, rr = b & 15, gg = rr & 7, top = rr >> 3;
                uint32_t a16 = (uint32_t)((((c * 4 + ks) * 2 + bhh) * 32 + gg * 4 + tg) * 16
                                          + (half * 2 + top) * 4);
                *reinterpret_cast<uint32_t*>(sm + a16)           = hv;
                *reinterpret_cast<uint32_t*>(sm + SM_A_LO + a16) = lv;
            }
        }
        __syncthreads();

        // ---- mainloop: 32 flat (c,ks) iterations, B via LDG, 1-ahead prefetch ----
        float d[4][4];
        #pragma unroll
        for (int a = 0; a < 4; ++a)
            #pragma unroll
            for (int b = 0; b < 4; ++b) d[a][b] = 0.0f;

        uint4 Bn0 = __ldg(reinterpret_cast<const uint4*>(wp));
        uint4 Bn1 = __ldg(reinterpret_cast<const uint4*>(wp + 2048));

        #pragma unroll 4
        for (int it = 0; it < 32; ++it) {
            const int c = it >> 2, ks = it & 3;
            uint4 B0 = Bn0, B1 = Bn1;
            if (it + 1 < 32) {
                const int it2 = it + 1;
                const uint8_t* q = wp + (it2 >> 2) * 32768 + (it2 & 3) * 512;
                Bn0 = __ldg(reinterpret_cast<const uint4*>(q));
                Bn1 = __ldg(reinterpret_cast<const uint4*>(q + 2048));
            }
            uint32_t ab = (uint32_t)((((c * 4 + ks) * 2 + bh) * 32 + lane) * 16);
            uint4 Ah = *reinterpret_cast<const uint4*>(sm + ab);
            uint4 Al = *reinterpret_cast<const uint4*>(sm + SM_A_LO + ab);
            mma16816(d[0], Ah.x, Ah.y, Ah.z, Ah.w, B0.x, B0.y);
            mma16816(d[0], Al.x, Al.y, Al.z, Al.w, B0.x, B0.y);
            mma16816(d[1], Ah.x, Ah.y, Ah.z, Ah.w, B0.z, B0.w);
            mma16816(d[1], Al.x, Al.y, Al.z, Al.w, B0.z, B0.w);
            mma16816(d[2], Ah.x, Ah.y, Ah.z, Ah.w, B1.x, B1.y);
            mma16816(d[2], Al.x, Al.y, Al.z, Al.w, B1.x, B1.y);
            mma16816(d[3], Ah.x, Ah.y, Ah.z, Ah.w, B1.z, B1.w);
            mma16816(d[3], Al.x, Al.y, Al.z, Al.w, B1.z, B1.w);
        }
        __syncthreads();

        // exchange preacts: d[nt] -> col = kc*32 + nt*8
        #pragma unroll
        for (int nt = 0; nt < 4; ++nt) {
            int col = kc * 32 + nt * 8 + tig * 2;
            int b = bh * 16 + gid;
            *reinterpret_cast<float2*>(s_pre + b * 260 + col)       = make_float2(d[nt][0], d[nt][1]);
            *reinterpret_cast<float2*>(s_pre + (b + 8) * 260 + col) = make_float2(d[nt][2], d[nt][3]);
        }
        __syncthreads();

        // ---- fused pointwise epilogue (R9-exact math) ----
        const float DT = 0.01f;
        const float A_OUT = 0.9900498337491681f;
        const float OMA_OUT = 0.009950166250831947f;
        #pragma unroll
        for (int o = 0; o < 4; ++o) {
            int b = eb0 + o * 8;
            float xb = x_s[b * 128 + t];
            float pj = s_pre[b * 260 +       ko] + xb * uj + bj;
            float pi = s_pre[b * 260 +  64 + ko] + xb * ui + bi2;
            float pf = s_pre[b * 260 + 128 + ko] + xb * uf + bf2;
            float po = s_pre[b * 260 + 192 + ko] + xb * uo + bo2;

            float j  = tanhf(pj);
            float ig = 1.0f / (1.0f + expf(-pi));
            float fg = 1.0f / (1.0f + expf(-pf));
            float og = 1.0f / (1.0f + expf(-po));

            float h_old = h32[b * 64 + ko];

            float xm = -7.8125e-5f * j;
            float alpha_m = 1.0f + xm + 0.5f * xm * xm;
            float xr = -1.5625e-4f * ig;
            float ro = 1.0f + xr + 0.5f * xr * xr;
            float b_ad = ro * 0.1f + (1.0f - ro) * ig;
            float Bth  = 0.04f + 1.8f * b_ad;
            float mem  = j * alpha_m + (1.0f - alpha_m) * h_old - Bth * ig * DT;
            float spike = (mem - Bth) > 0.0f ? 1.0f : 0.0f;
            float mem_out = mem * A_OUT + OMA_OUT * spike + 0.08f;

            float c_new = creg[o] * fg + ig * spike * mem_out;
            creg[o] = c_new;
            float h_new = og * tanhf(c_new);
            h32[b * 64 + ko] = h_new;                       // own slice, own slot
            p.out[(((size_t)b * T_STEPS + t) * I_CH + i) * N_DIM + kg] = h_new;
            if (t == T_STEPS - 1) {
                float* h_fin = p.out + (size_t)B_SZ * T_STEPS * I_CH * N_DIM;
                float* c_fin = h_fin + B_SZ * I_CH * N_DIM;
                size_t fidx = ((size_t)b * I_CH + i) * N_DIM + kg;
                h_fin[fidx] = h_new;
                c_fin[fidx] = c_new;
            }
        }

        // ---- per-channel barrier (8 CTAs of channel i) ----
        if (t + 1 < T_STEPS) {
            __threadfence();
            __syncthreads();
            if (tid == 0) {
                atomicAdd(bar, 1u);
                unsigned target = (unsigned)(t + 1) * 8u;
                unsigned v;
                do {
                    asm volatile("ld.acquire.gpu.u32 %0, [%1];"
                                 : "=r"(v) : "l"(bar) : "memory");
                } while (v < target);
            }
            __syncthreads();
        }
    }
}

extern "C" void kernel_launch(void* const* d_in, const int* in_sizes, int n_in,
                              void* d_out, int out_size) {
    Params p;
    p.x = (const float*)d_in[0];
    for (int g = 0; g < 4; ++g) {
        p.U[g]    = (const float*)d_in[1 + g];
        p.W[g]    = (const float*)d_in[5 + g];
        p.bias[g] = (const float*)d_in[9 + g];
    }
    p.out = (float*)d_out;

    cudaFuncSetAttribute(persist_kernel, cudaFuncAttributeMaxDynamicSharedMemorySize, SM_TOT);

    prep_kernel<<<128, 256>>>(p);                 // also resets barriers each replay
    dim3 grid(8, I_CH);                           // 128 blocks, all co-resident
    persist_kernel<<<grid, 512, SM_TOT>>>(p);
}

// round 12
// speedup vs baseline: 1.1085x; 1.0913x over previous
#include <cuda_runtime.h>
#include <cuda_fp16.h>
#include <stdint.h>
#include <math.h>

#define B_SZ    32
#define T_STEPS 128
#define I_CH    16
#define N_DIM   512

// ---------------- scratch ----------------
// W image (fp16): 128 blobs (i*8+kt) x 256KB; blob = 8 chunks (64 n) x 32KB.
// addr(c,ks,pp) per warp: blob + kc*4096 + lane*16 + c*32768 + pp*2048 + ks*512
// unit = {b0(col_a),b1(col_a),b0(col_b),b1(col_b)}, col_a = kc*32+pp*16+gid, col_b = col_a+8.
__device__ __align__(128) uint8_t g_wimg[128 * 262144];
__device__ unsigned int g_bar;

struct Params {
    const float* x;
    const float* U[4];
    const float* W[4];
    const float* bias[4];
    float* out;
};

// ---------------- helpers ----------------
__device__ __forceinline__ void mma16816(float* d, uint32_t a0, uint32_t a1, uint32_t a2,
                                         uint32_t a3, uint32_t b0, uint32_t b1) {
    asm volatile(
        "mma.sync.aligned.m16n8k16.row.col.f32.f16.f16.f32 "
        "{%0,%1,%2,%3}, {%4,%5,%6,%7}, {%8,%9}, {%0,%1,%2,%3};"
        : "+f"(d[0]), "+f"(d[1]), "+f"(d[2]), "+f"(d[3])
        : "r"(a0), "r"(a1), "r"(a2), "r"(a3), "r"(b0), "r"(b1));
}
__device__ __forceinline__ uint32_t packh(float x, float y) {
    __half hx = __float2half_rn(x), hy = __float2half_rn(y);
    return (uint32_t)__half_as_ushort(hx) | ((uint32_t)__half_as_ushort(hy) << 16);
}

// ---------------- prep: transpose + fp16-pack W; reset barrier ----------------
__global__ __launch_bounds__(256) void prep_kernel(Params p) {
    __shared__ float ts[128 * 68];     // [n 128][ko 64 + pad]
    int blob = blockIdx.x;             // 0..127
    int i = blob >> 3, kt = blob & 7;
    if (blob == 0 && threadIdx.x == 0) g_bar = 0;
    int m0 = kt * 64;
    uint8_t* dst = g_wimg + (size_t)blob * 262144;
    int tid = threadIdx.x;

    for (int g = 0; g < 4; ++g) {
        const float* W = p.W[g] + (size_t)i * N_DIM * N_DIM;
        for (int nb = 0; nb < 4; ++nb) {            // 128-n groups
            __syncthreads();
            #pragma unroll
            for (int o = 0; o < 8; ++o) {
                int e = o * 256 + tid;              // 2048 float4 = 128 n x 16
                int row = e >> 4, q = e & 15;
                float4 v = *reinterpret_cast<const float4*>(
                    W + (size_t)(nb * 128 + row) * N_DIM + m0 + q * 4);
                float* sp = ts + row * 68 + q * 4;
                sp[0] = v.x; sp[1] = v.y; sp[2] = v.z; sp[3] = v.w;
            }
            __syncthreads();
            #pragma unroll
            for (int o = 0; o < 4; ++o) {
                int idx = o * 256 + tid;            // 1024 units per (g, nb)
                int cl  = idx >> 9;                 // local chunk (64 n each)
                int r   = idx & 511;
                int kcl = (r >> 8) & 1, pp = (r >> 7) & 1;
                int ks  = (r >> 5) & 3, lane = r & 31;
                int gid = lane >> 2, tig = lane & 3;
                int ko_a = kcl * 32 + pp * 16 + gid;
                int ko_b = ko_a + 8;
                int n0 = cl * 64 + ks * 16 + tig * 2;
                uint4 u;
                u.x = packh(ts[n0 * 68 + ko_a],       ts[(n0 + 1) * 68 + ko_a]);
                u.y = packh(ts[(n0 + 8) * 68 + ko_a], ts[(n0 + 9) * 68 + ko_a]);
                u.z = packh(ts[n0 * 68 + ko_b],       ts[(n0 + 1) * 68 + ko_b]);
                u.w = packh(ts[(n0 + 8) * 68 + ko_b], ts[(n0 + 9) * 68 + ko_b]);
                int kc = 2 * g + kcl;
                int chunk = nb * 2 + cl;
                *reinterpret_cast<uint4*>(
                    dst + (size_t)chunk * 32768
                        + ((((kc * 2 + pp) * 4 + ks) * 32 + lane) << 4)) = u;
            }
        }
    }
}

// ---------------- persistent kernel ----------------
// dyn SMEM: A_hi @0 (32K) | A_lo @32768 | h32 @65536 (8K) | s_pre @73728 (33280) | ub @107008 (2K)
// A unit (16B) at (((c*4+ks)*2+bh)*32 + lane)*16
#define SM_A_LO 32768
#define SM_H32  65536
#define SM_PRE  73728
#define SM_UB   107008
#define SM_TOT  109056

__global__ __launch_bounds__(512, 1) void persist_kernel(Params p) {
    const int kt = blockIdx.x;   // 0..7 (64-wide k_out tile)
    const int i  = blockIdx.y;   // 0..15
    extern __shared__ __align__(16) uint8_t sm[];
    const uint8_t* blob = g_wimg + (size_t)(i * 8 + kt) * 262144;
    const int tid = threadIdx.x;

    const int lane = tid & 31, w = tid >> 5;
    const int bh = w & 1, kc = w >> 1;          // kc 0..7
    const int gid = lane >> 2, tig = lane & 3;

    // per-warp B base: addr(c,ks,pp) = wp + c*32768 + pp*2048 + ks*512
    const uint8_t* wp = blob + kc * 4096 + lane * 16;

    // epilogue ownership
    const int ko = tid & 63;
    const int kg = kt * 64 + ko;
    const int eb0 = tid >> 6;                   // 0..7
    float creg[4] = {0.f, 0.f, 0.f, 0.f};

    float* h32   = reinterpret_cast<float*>(sm + SM_H32);
    float* s_pre = reinterpret_cast<float*>(sm + SM_PRE);   // [32][260]
    float* u_s   = reinterpret_cast<float*>(sm + SM_UB);    // [4][64]
    float* b_s   = u_s + 256;                               // [4][64]

    // U/bias into smem once (frees 8 regs/thread)
    if (tid < 256) {
        int g = tid >> 6, kk = tid & 63;
        u_s[tid] = p.U[g][i * N_DIM + kt * 64 + kk];
    } else {
        int r = tid - 256;
        int g = r >> 6, kk = r & 63;
        b_s[r] = p.bias[g][i * N_DIM + kt * 64 + kk];
    }

    for (int t = 0; t < T_STEPS; ++t) {
        float xv[4];
        #pragma unroll
        for (int o = 0; o < 4; ++o)
            xv[o] = __ldg(&p.x[((size_t)(eb0 + o * 8) * T_STEPS + t) * I_CH + i]);

        // ---- stage A (h split fp16) + h32 ----
        if (t == 0) {
            #pragma unroll
            for (int o = 0; o < 9; ++o)
                reinterpret_cast<uint4*>(sm)[o * 512 + tid] = make_uint4(0, 0, 0, 0);
        } else {
            #pragma unroll
            for (int o = 0; o < 16; ++o) {
                int pr = o * 512 + tid;           // 8192 pairs: b(32) x P(256)
                int b = pr >> 8, P = pr & 255;
                float2 v = __ldcg(reinterpret_cast<const float2*>(
                    p.out + (((size_t)b * T_STEPS + (t - 1)) * I_CH + i) * N_DIM + P * 2));
                __half h0 = __float2half_rn(v.x), h1 = __float2half_rn(v.y);
                uint32_t hv = (uint32_t)__half_as_ushort(h0) |
                              ((uint32_t)__half_as_ushort(h1) << 16);
                uint32_t lv = packh(v.x - __half2float(h0), v.y - __half2float(h1));
                int c = P >> 5;
                int ks = (P >> 3) & 3, half = (P >> 2) & 1, tg = P & 3;
                int bhh = b >> 4, rr = b & 15, gg = rr & 7, top = rr >> 3;
                uint32_t a16 = (uint32_t)((((c * 4 + ks) * 2 + bhh) * 32 + gg * 4 + tg) * 16
                                          + (half * 2 + top) * 4);
                *reinterpret_cast<uint32_t*>(sm + a16)           = hv;
                *reinterpret_cast<uint32_t*>(sm + SM_A_LO + a16) = lv;
                int Pl = P - kt * 32;
                if (Pl >= 0 && Pl < 32)
                    *reinterpret_cast<float2*>(h32 + b * 64 + Pl * 2) = v;
            }
        }
        __syncthreads();

        // ---- mainloop: 32 flat (c,ks) iterations, B via LDG, 3-deep register pipeline ----
        float d[4][4];
        #pragma unroll
        for (int a = 0; a < 4; ++a)
            #pragma unroll
            for (int b = 0; b < 4; ++b) d[a][b] = 0.0f;

        uint4 Bp[3][2];
        #pragma unroll
        for (int s = 0; s < 3; ++s) {
            const uint8_t* q = wp + s * 512;     // c=0 for s<4
            Bp[s][0] = __ldg(reinterpret_cast<const uint4*>(q));
            Bp[s][1] = __ldg(reinterpret_cast<const uint4*>(q + 2048));
        }

        #pragma unroll
        for (int it = 0; it < 32; ++it) {
            const int c = it >> 2, ks = it & 3;
            const int sl = it % 3;
            uint4 B0 = Bp[sl][0], B1 = Bp[sl][1];
            if (it + 3 < 32) {
                const int it2 = it + 3;
                const uint8_t* q = wp + (it2 >> 2) * 32768 + (it2 & 3) * 512;
                Bp[sl][0] = __ldg(reinterpret_cast<const uint4*>(q));
                Bp[sl][1] = __ldg(reinterpret_cast<const uint4*>(q + 2048));
            }
            uint32_t ab = (uint32_t)((((c * 4 + ks) * 2 + bh) * 32 + lane) * 16);
            uint4 Ah = *reinterpret_cast<const uint4*>(sm + ab);
            uint4 Al = *reinterpret_cast<const uint4*>(sm + SM_A_LO + ab);
            mma16816(d[0], Ah.x, Ah.y, Ah.z, Ah.w, B0.x, B0.y);
            mma16816(d[0], Al.x, Al.y, Al.z, Al.w, B0.x, B0.y);
            mma16816(d[1], Ah.x, Ah.y, Ah.z, Ah.w, B0.z, B0.w);
            mma16816(d[1], Al.x, Al.y, Al.z, Al.w, B0.z, B0.w);
            mma16816(d[2], Ah.x, Ah.y, Ah.z, Ah.w, B1.x, B1.y);
            mma16816(d[2], Al.x, Al.y, Al.z, Al.w, B1.x, B1.y);
            mma16816(d[3], Ah.x, Ah.y, Ah.z, Ah.w, B1.z, B1.w);
            mma16816(d[3], Al.x, Al.y, Al.z, Al.w, B1.z, B1.w);
        }
        __syncthreads();

        // exchange preacts: d[nt] -> col = kc*32 + nt*8
        #pragma unroll
        for (int nt = 0; nt < 4; ++nt) {
            int col = kc * 32 + nt * 8 + tig * 2;
            int b = bh * 16 + gid;
            *reinterpret_cast<float2*>(s_pre + b * 260 + col)       = make_float2(d[nt][0], d[nt][1]);
            *reinterpret_cast<float2*>(s_pre + (b + 8) * 260 + col) = make_float2(d[nt][2], d[nt][3]);
        }
        __syncthreads();

        // ---- fused pointwise epilogue (R9-exact math) ----
        const float DT = 0.01f;
        const float A_OUT = 0.9900498337491681f;
        const float OMA_OUT = 0.009950166250831947f;
        #pragma unroll
        for (int o = 0; o < 4; ++o) {
            int b = eb0 + o * 8;
            float xb = xv[o];
            float pj = s_pre[b * 260 +       ko] + xb * u_s[ko]       + b_s[ko];
            float pi = s_pre[b * 260 +  64 + ko] + xb * u_s[64 + ko]  + b_s[64 + ko];
            float pf = s_pre[b * 260 + 128 + ko] + xb * u_s[128 + ko] + b_s[128 + ko];
            float po = s_pre[b * 260 + 192 + ko] + xb * u_s[192 + ko] + b_s[192 + ko];

            float j  = tanhf(pj);
            float ig = 1.0f / (1.0f + expf(-pi));
            float fg = 1.0f / (1.0f + expf(-pf));
            float og = 1.0f / (1.0f + expf(-po));

            float h_old = h32[b * 64 + ko];

            float xm = -7.8125e-5f * j;
            float alpha_m = 1.0f + xm + 0.5f * xm * xm;
            float xr = -1.5625e-4f * ig;
            float ro = 1.0f + xr + 0.5f * xr * xr;
            float b_ad = ro * 0.1f + (1.0f - ro) * ig;
            float Bth  = 0.04f + 1.8f * b_ad;
            float mem  = j * alpha_m + (1.0f - alpha_m) * h_old - Bth * ig * DT;
            float spike = (mem - Bth) > 0.0f ? 1.0f : 0.0f;
            float mem_out = mem * A_OUT + OMA_OUT * spike + 0.08f;

            float c_new = creg[o] * fg + ig * spike * mem_out;
            creg[o] = c_new;
            float h_new = og * tanhf(c_new);
            p.out[(((size_t)b * T_STEPS + t) * I_CH + i) * N_DIM + kg] = h_new;
            if (t == T_STEPS - 1) {
                float* h_fin = p.out + (size_t)B_SZ * T_STEPS * I_CH * N_DIM;
                float* c_fin = h_fin + B_SZ * I_CH * N_DIM;
                size_t fidx = ((size_t)b * I_CH + i) * N_DIM + kg;
                h_fin[fidx] = h_new;
                c_fin[fidx] = c_new;
            }
        }

        // ---- grid barrier (128 CTAs, all co-resident) ----
        if (t + 1 < T_STEPS) {
            __threadfence();
            __syncthreads();
            if (tid == 0) {
                atomicAdd(&g_bar, 1u);
                unsigned target = (unsigned)(t + 1) * 128u;
                unsigned v;
                do {
                    asm volatile("ld.acquire.gpu.u32 %0, [%1];"
                                 : "=r"(v) : "l"(&g_bar) : "memory");
                } while (v < target);
            }
            __syncthreads();
        }
    }
}

extern "C" void kernel_launch(void* const* d_in, const int* in_sizes, int n_in,
                              void* d_out, int out_size) {
    Params p;
    p.x = (const float*)d_in[0];
    for (int g = 0; g < 4; ++g) {
        p.U[g]    = (const float*)d_in[1 + g];
        p.W[g]    = (const float*)d_in[5 + g];
        p.bias[g] = (const float*)d_in[9 + g];
    }
    p.out = (float*)d_out;

    cudaFuncSetAttribute(persist_kernel, cudaFuncAttributeMaxDynamicSharedMemorySize, SM_TOT);

    prep_kernel<<<128, 256>>>(p);                 // also resets g_bar each replay
    dim3 grid(8, I_CH);                           // 128 blocks, all co-resident
    persist_kernel<<<grid, 512, SM_TOT>>>(p);
}

// round 13
// speedup vs baseline: 1.2093x; 1.0909x over previous
#include <cuda_runtime.h>
#include <cuda_fp16.h>
#include <stdint.h>
#include <math.h>

#define B_SZ    32
#define T_STEPS 128
#define I_CH    16
#define N_DIM   512

// ---------------- scratch ----------------
// W image (fp16): 128 blobs (i*8+kt) x 256KB; blob = 8 chunks (c = 64-n group) x 32KB.
// Fragment unit address: blob + c*32768 + ks*8192 + q*1024 + u*512 + lane*16  (+ (g&1)*8 half)
// unit u=0 holds {b0(g0),b1(g0),b0(g1),b1(g1)}, u=1 holds {g2,g3}; col(g) = g*64 + q*8 + gid,
// k-slice n0 = c*64 + ks*16 + tig*2: b0 = W[n0,n0+1][col], b1 = W[n0+8,n0+9][col].
__device__ __align__(128) uint8_t g_wimg[128 * 262144];
__device__ unsigned int g_bar;

struct Params {
    const float* x;
    const float* U[4];
    const float* W[4];
    const float* bias[4];
    float* out;
};

// ---------------- helpers ----------------
__device__ __forceinline__ void mma16816(float* d, uint32_t a0, uint32_t a1, uint32_t a2,
                                         uint32_t a3, uint32_t b0, uint32_t b1) {
    asm volatile(
        "mma.sync.aligned.m16n8k16.row.col.f32.f16.f16.f32 "
        "{%0,%1,%2,%3}, {%4,%5,%6,%7}, {%8,%9}, {%0,%1,%2,%3};"
        : "+f"(d[0]), "+f"(d[1]), "+f"(d[2]), "+f"(d[3])
        : "r"(a0), "r"(a1), "r"(a2), "r"(a3), "r"(b0), "r"(b1));
}
__device__ __forceinline__ uint32_t packh(float x, float y) {
    __half hx = __float2half_rn(x), hy = __float2half_rn(y);
    return (uint32_t)__half_as_ushort(hx) | ((uint32_t)__half_as_ushort(hy) << 16);
}

// ---------------- prep: transpose + fp16-pack W (gate-interleaved units); reset barrier ----------------
__global__ __launch_bounds__(256) void prep_kernel(Params p) {
    __shared__ float ts[128 * 68];     // [n 128][ko 64 + pad]
    int blob = blockIdx.x;             // 0..127
    int i = blob >> 3, kt = blob & 7;
    if (blob == 0 && threadIdx.x == 0) g_bar = 0;
    int m0 = kt * 64;
    uint8_t* dst = g_wimg + (size_t)blob * 262144;
    int tid = threadIdx.x;

    for (int g = 0; g < 4; ++g) {
        const float* W = p.W[g] + (size_t)i * N_DIM * N_DIM;
        for (int nb = 0; nb < 4; ++nb) {            // 128-n groups
            __syncthreads();
            #pragma unroll
            for (int o = 0; o < 8; ++o) {
                int e = o * 256 + tid;              // 2048 float4 = 128 n x 16
                int row = e >> 4, qq = e & 15;
                float4 v = *reinterpret_cast<const float4*>(
                    W + (size_t)(nb * 128 + row) * N_DIM + m0 + qq * 4);
                float* sp = ts + row * 68 + qq * 4;
                sp[0] = v.x; sp[1] = v.y; sp[2] = v.z; sp[3] = v.w;
            }
            __syncthreads();
            #pragma unroll
            for (int o = 0; o < 8; ++o) {
                int idx = o * 256 + tid;            // 2048 fragment-halves per (g, nb)
                int cl  = idx >> 10;                // local 64-n chunk 0..1
                int r   = idx & 1023;
                int ks  = r >> 8;                   // 0..3
                int q   = (r >> 5) & 7;             // 0..7
                int lane = r & 31;
                int gid = lane >> 2, tig = lane & 3;
                int ko  = q * 8 + gid;              // 0..63
                int n0  = cl * 64 + ks * 16 + tig * 2;
                uint2 u;
                u.x = packh(ts[n0 * 68 + ko],       ts[(n0 + 1) * 68 + ko]);
                u.y = packh(ts[(n0 + 8) * 68 + ko], ts[(n0 + 9) * 68 + ko]);
                int chunk = nb * 2 + cl;
                int uu = g >> 1;
                uint32_t off = (uint32_t)(chunk * 32768 + ks * 8192 + q * 1024
                                          + uu * 512 + lane * 16 + (g & 1) * 8);
                *reinterpret_cast<uint2*>(dst + off) = u;
            }
        }
    }
}

// ---------------- persistent kernel ----------------
// dyn SMEM: A_hi @0 (32K) | A_lo @32768 (32K). A unit (16B) at ((it*2+bh)*32 + lane)*16
#define SM_A_LO 32768
#define SM_TOT  65536

__global__ __launch_bounds__(512, 1) void persist_kernel(Params p) {
    const int kt = blockIdx.x;   // 0..7 (64-wide k_out tile)
    const int i  = blockIdx.y;   // 0..15
    extern __shared__ __align__(16) uint8_t sm[];
    const uint8_t* blob = g_wimg + (size_t)(i * 8 + kt) * 262144;
    const int tid = threadIdx.x;

    const int lane = tid & 31, w = tid >> 5;
    const int bh = w & 1, q = w >> 1;           // q = 8-col group 0..7
    const int gid = lane >> 2, tig = lane & 3;

    // per-warp B base
    const uint8_t* wq = blob + q * 1024 + lane * 16;

    // epilogue ownership (fixed over t): batches {b0, b0+8}, cols {kg0, kg0+1}
    const int b0  = bh * 16 + gid;
    const int kg0 = kt * 64 + q * 8 + tig * 2;

    float Uv[4][2], Bv[4][2];
    #pragma unroll
    for (int g = 0; g < 4; ++g) {
        Uv[g][0] = p.U[g][i * N_DIM + kg0];     Uv[g][1] = p.U[g][i * N_DIM + kg0 + 1];
        Bv[g][0] = p.bias[g][i * N_DIM + kg0];  Bv[g][1] = p.bias[g][i * N_DIM + kg0 + 1];
    }
    float creg[4] = {0.f, 0.f, 0.f, 0.f};
    float hreg[4] = {0.f, 0.f, 0.f, 0.f};
    float xc0 = __ldg(&p.x[((size_t)b0 * T_STEPS) * I_CH + i]);
    float xc1 = __ldg(&p.x[((size_t)(b0 + 8) * T_STEPS) * I_CH + i]);

    // prime 4-deep B pipeline (it = 0..3); wrap-around keeps it full across steps
    uint4 Bp[4][2];
    #pragma unroll
    for (int s = 0; s < 4; ++s) {
        const uint8_t* qp = wq + (s & 3) * 8192;   // c=0
        Bp[s][0] = __ldg(reinterpret_cast<const uint4*>(qp));
        Bp[s][1] = __ldg(reinterpret_cast<const uint4*>(qp + 512));
    }

    for (int t = 0; t < T_STEPS; ++t) {
        // ---- stage A (h split fp16) ----
        if (t == 0) {
            #pragma unroll
            for (int o = 0; o < 8; ++o)
                reinterpret_cast<uint4*>(sm)[o * 512 + tid] = make_uint4(0, 0, 0, 0);
        } else {
            #pragma unroll
            for (int o = 0; o < 16; ++o) {
                int pr = o * 512 + tid;           // 8192 pairs: b(32) x P(256)
                int b = pr >> 8, P = pr & 255;
                float2 v = __ldcg(reinterpret_cast<const float2*>(
                    p.out + (((size_t)b * T_STEPS + (t - 1)) * I_CH + i) * N_DIM + P * 2));
                __half h0 = __float2half_rn(v.x), h1 = __float2half_rn(v.y);
                uint32_t hv = (uint32_t)__half_as_ushort(h0) |
                              ((uint32_t)__half_as_ushort(h1) << 16);
                uint32_t lv = packh(v.x - __half2float(h0), v.y - __half2float(h1));
                int c = P >> 5;
                int ks = (P >> 3) & 3, half = (P >> 2) & 1, tg = P & 3;
                int bhh = b >> 4, rr = b & 15, gg = rr & 7, top = rr >> 3;
                uint32_t a16 = (uint32_t)((((c * 4 + ks) * 2 + bhh) * 32 + gg * 4 + tg) * 16
                                          + (half * 2 + top) * 4);
                *reinterpret_cast<uint32_t*>(sm + a16)           = hv;
                *reinterpret_cast<uint32_t*>(sm + SM_A_LO + a16) = lv;
            }
        }
        __syncthreads();

        // ---- mainloop: 32 flat (c,ks) iterations, 4-deep wrap-around B pipeline ----
        float d[4][4];
        #pragma unroll
        for (int a = 0; a < 4; ++a)
            #pragma unroll
            for (int b = 0; b < 4; ++b) d[a][b] = 0.0f;

        #pragma unroll
        for (int it = 0; it < 32; ++it) {
            const int sl = it & 3;
            uint4 U0 = Bp[sl][0], U1 = Bp[sl][1];
            {
                const int it2 = (it + 4) & 31;    // wraps to next step's head at tail
                const uint8_t* qp = wq + (it2 >> 2) * 32768 + (it2 & 3) * 8192;
                Bp[sl][0] = __ldg(reinterpret_cast<const uint4*>(qp));
                Bp[sl][1] = __ldg(reinterpret_cast<const uint4*>(qp + 512));
            }
            uint32_t ab = (uint32_t)(((it * 2 + bh) * 32 + lane) * 16);
            uint4 Ah = *reinterpret_cast<const uint4*>(sm + ab);
            uint4 Al = *reinterpret_cast<const uint4*>(sm + SM_A_LO + ab);
            mma16816(d[0], Ah.x, Ah.y, Ah.z, Ah.w, U0.x, U0.y);
            mma16816(d[0], Al.x, Al.y, Al.z, Al.w, U0.x, U0.y);
            mma16816(d[1], Ah.x, Ah.y, Ah.z, Ah.w, U0.z, U0.w);
            mma16816(d[1], Al.x, Al.y, Al.z, Al.w, U0.z, U0.w);
            mma16816(d[2], Ah.x, Ah.y, Ah.z, Ah.w, U1.x, U1.y);
            mma16816(d[2], Al.x, Al.y, Al.z, Al.w, U1.x, U1.y);
            mma16816(d[3], Ah.x, Ah.y, Ah.z, Ah.w, U1.z, U1.w);
            mma16816(d[3], Al.x, Al.y, Al.z, Al.w, U1.z, U1.w);
        }

        // prefetch next-step x (pre-barrier, independent)
        float xn0 = 0.f, xn1 = 0.f;
        if (t + 1 < T_STEPS) {
            xn0 = __ldg(&p.x[((size_t)b0 * T_STEPS + t + 1) * I_CH + i]);
            xn1 = __ldg(&p.x[((size_t)(b0 + 8) * T_STEPS + t + 1) * I_CH + i]);
        }

        // ---- register-resident pointwise epilogue ----
        const float DT = 0.01f;
        const float A_OUT = 0.9900498337491681f;
        const float OMA_OUT = 0.009950166250831947f;
        #pragma unroll
        for (int rb = 0; rb < 2; ++rb) {
            int b = b0 + rb * 8;
            float xb = rb ? xc1 : xc0;
            float2 hv;
            #pragma unroll
            for (int rc = 0; rc < 2; ++rc) {
                int e = rb * 2 + rc;
                float pj = d[0][e] + xb * Uv[0][rc] + Bv[0][rc];
                float pi = d[1][e] + xb * Uv[1][rc] + Bv[1][rc];
                float pf = d[2][e] + xb * Uv[2][rc] + Bv[2][rc];
                float po = d[3][e] + xb * Uv[3][rc] + Bv[3][rc];

                float j  = tanhf(pj);
                float ig = 1.0f / (1.0f + expf(-pi));
                float fg = 1.0f / (1.0f + expf(-pf));
                float og = 1.0f / (1.0f + expf(-po));

                float h_old = hreg[e];
                float xm = -7.8125e-5f * j;
                float alpha_m = 1.0f + xm + 0.5f * xm * xm;
                float xr = -1.5625e-4f * ig;
                float ro = 1.0f + xr + 0.5f * xr * xr;
                float b_ad = ro * 0.1f + (1.0f - ro) * ig;
                float Bth  = 0.04f + 1.8f * b_ad;
                float mem  = j * alpha_m + (1.0f - alpha_m) * h_old - Bth * ig * DT;
                float spike = (mem - Bth) > 0.0f ? 1.0f : 0.0f;
                float mem_out = mem * A_OUT + OMA_OUT * spike + 0.08f;

                float c_new = creg[e] * fg + ig * spike * mem_out;
                creg[e] = c_new;
                float h_new = og * tanhf(c_new);
                hreg[e] = h_new;
                if (rc == 0) hv.x = h_new; else hv.y = h_new;
            }
            *reinterpret_cast<float2*>(
                p.out + (((size_t)b * T_STEPS + t) * I_CH + i) * N_DIM + kg0) = hv;
            if (t == T_STEPS - 1) {
                float* h_fin = p.out + (size_t)B_SZ * T_STEPS * I_CH * N_DIM;
                float* c_fin = h_fin + B_SZ * I_CH * N_DIM;
                size_t fidx = ((size_t)b * I_CH + i) * N_DIM + kg0;
                *reinterpret_cast<float2*>(h_fin + fidx) = hv;
                *reinterpret_cast<float2*>(c_fin + fidx) =
                    make_float2(creg[rb * 2], creg[rb * 2 + 1]);
            }
        }
        xc0 = xn0; xc1 = xn1;

        // ---- grid barrier (128 CTAs, all co-resident) ----
        if (t + 1 < T_STEPS) {
            __threadfence();
            __syncthreads();
            if (tid == 0) {
                atomicAdd(&g_bar, 1u);
                unsigned target = (unsigned)(t + 1) * 128u;
                unsigned v;
                do {
                    asm volatile("ld.acquire.gpu.u32 %0, [%1];"
                                 : "=r"(v) : "l"(&g_bar) : "memory");
                } while (v < target);
            }
            __syncthreads();
        }
    }
}

extern "C" void kernel_launch(void* const* d_in, const int* in_sizes, int n_in,
                              void* d_out, int out_size) {
    Params p;
    p.x = (const float*)d_in[0];
    for (int g = 0; g < 4; ++g) {
        p.U[g]    = (const float*)d_in[1 + g];
        p.W[g]    = (const float*)d_in[5 + g];
        p.bias[g] = (const float*)d_in[9 + g];
    }
    p.out = (float*)d_out;

    cudaFuncSetAttribute(persist_kernel, cudaFuncAttributeMaxDynamicSharedMemorySize, SM_TOT);

    prep_kernel<<<128, 256>>>(p);                 // also resets g_bar each replay
    dim3 grid(8, I_CH);                           // 128 blocks, all co-resident
    persist_kernel<<<grid, 512, SM_TOT>>>(p);
}

// round 14
// speedup vs baseline: 1.3190x; 1.0907x over previous
#include <cuda_runtime.h>
#include <cuda_fp16.h>
#include <stdint.h>
#include <math.h>

#define B_SZ    32
#define T_STEPS 128
#define I_CH    16
#define N_DIM   512

// ---------------- scratch ----------------
// W image (fp16): 128 blobs (i*8+kt) x 256KB; blob = 8 chunks (c = 64-n group) x 32KB.
// Fragment unit address: blob + c*32768 + ks*8192 + q*1024 + u*512 + lane*16  (+ (g&1)*8 half)
// unit u=0 holds {b0(g0),b1(g0),b0(g1),b1(g1)}, u=1 holds {g2,g3}; col(g) = g*64 + q*8 + gid,
// k-slice n0 = c*64 + ks*16 + tig*2: b0 = W[n0,n0+1][col], b1 = W[n0+8,n0+9][col].
__device__ __align__(128) uint8_t g_wimg[128 * 262144];
// h fragments (producer-packed): per channel 64KB (hi @0, lo @32768), same layout as SMEM A.
__device__ __align__(128) uint8_t g_hfrag[16 * 65536];
__device__ unsigned int g_bar;

struct Params {
    const float* x;
    const float* U[4];
    const float* W[4];
    const float* bias[4];
    float* out;
};

// ---------------- helpers ----------------
__device__ __forceinline__ void mma16816(float* d, uint32_t a0, uint32_t a1, uint32_t a2,
                                         uint32_t a3, uint32_t b0, uint32_t b1) {
    asm volatile(
        "mma.sync.aligned.m16n8k16.row.col.f32.f16.f16.f32 "
        "{%0,%1,%2,%3}, {%4,%5,%6,%7}, {%8,%9}, {%0,%1,%2,%3};"
        : "+f"(d[0]), "+f"(d[1]), "+f"(d[2]), "+f"(d[3])
        : "r"(a0), "r"(a1), "r"(a2), "r"(a3), "r"(b0), "r"(b1));
}
__device__ __forceinline__ uint32_t packh(float x, float y) {
    __half hx = __float2half_rn(x), hy = __float2half_rn(y);
    return (uint32_t)__half_as_ushort(hx) | ((uint32_t)__half_as_ushort(hy) << 16);
}

// ---------------- prep: transpose + fp16-pack W; zero h-frag scratch; reset barrier ----------------
__global__ __launch_bounds__(256) void prep_kernel(Params p) {
    __shared__ float ts[128 * 68];     // [n 128][ko 64 + pad]
    int blob = blockIdx.x;             // 0..127
    int i = blob >> 3, kt = blob & 7;
    if (blob == 0 && threadIdx.x == 0) g_bar = 0;
    int m0 = kt * 64;
    uint8_t* dst = g_wimg + (size_t)blob * 262144;
    int tid = threadIdx.x;

    // zero this blob's share of g_hfrag (1MB / 128 blocks = 8KB)
    {
        uint4* z = reinterpret_cast<uint4*>(g_hfrag + (size_t)blob * 8192);
        z[tid] = make_uint4(0, 0, 0, 0);
        z[256 + tid] = make_uint4(0, 0, 0, 0);
    }

    for (int g = 0; g < 4; ++g) {
        const float* W = p.W[g] + (size_t)i * N_DIM * N_DIM;
        for (int nb = 0; nb < 4; ++nb) {            // 128-n groups
            __syncthreads();
            #pragma unroll
            for (int o = 0; o < 8; ++o) {
                int e = o * 256 + tid;              // 2048 float4 = 128 n x 16
                int row = e >> 4, qq = e & 15;
                float4 v = *reinterpret_cast<const float4*>(
                    W + (size_t)(nb * 128 + row) * N_DIM + m0 + qq * 4);
                float* sp = ts + row * 68 + qq * 4;
                sp[0] = v.x; sp[1] = v.y; sp[2] = v.z; sp[3] = v.w;
            }
            __syncthreads();
            #pragma unroll
            for (int o = 0; o < 8; ++o) {
                int idx = o * 256 + tid;            // 2048 fragment-halves per (g, nb)
                int cl  = idx >> 10;                // local 64-n chunk 0..1
                int r   = idx & 1023;
                int ks  = r >> 8;                   // 0..3
                int q   = (r >> 5) & 7;             // 0..7
                int lane = r & 31;
                int gid = lane >> 2, tig = lane & 3;
                int ko  = q * 8 + gid;              // 0..63
                int n0  = cl * 64 + ks * 16 + tig * 2;
                uint2 u;
                u.x = packh(ts[n0 * 68 + ko],       ts[(n0 + 1) * 68 + ko]);
                u.y = packh(ts[(n0 + 8) * 68 + ko], ts[(n0 + 9) * 68 + ko]);
                int chunk = nb * 2 + cl;
                int uu = g >> 1;
                uint32_t off = (uint32_t)(chunk * 32768 + ks * 8192 + q * 1024
                                          + uu * 512 + lane * 16 + (g & 1) * 8);
                *reinterpret_cast<uint2*>(dst + off) = u;
            }
        }
    }
}

// ---------------- persistent kernel ----------------
// dyn SMEM: A_hi @0 (32K) | A_lo @32768 (32K). A unit (16B) at ((it*2+bh)*32 + lane)*16
#define SM_A_LO 32768
#define SM_TOT  65536

__global__ __launch_bounds__(512, 1) void persist_kernel(Params p) {
    const int kt = blockIdx.x;   // 0..7 (64-wide k_out tile)
    const int i  = blockIdx.y;   // 0..15
    extern __shared__ __align__(16) uint8_t sm[];
    const uint8_t* blob = g_wimg + (size_t)(i * 8 + kt) * 262144;
    const int tid = threadIdx.x;

    const int lane = tid & 31, w = tid >> 5;
    const int bh = w & 1, q = w >> 1;           // q = 8-col group 0..7
    const int gid = lane >> 2, tig = lane & 3;

    // per-warp B base
    const uint8_t* wq = blob + q * 1024 + lane * 16;

    // epilogue ownership (fixed over t): batches {b0, b0+8}, cols {kg0, kg0+1}
    const int b0  = bh * 16 + gid;
    const int kg0 = kt * 64 + q * 8 + tig * 2;

    // h-fragment scratch address this thread produces (both tops contiguous, 8B)
    uint8_t* hf_ch = g_hfrag + (size_t)i * 65536;
    const int ks2 = (4 * q + tig) >> 3;
    const uint32_t a16b = (uint32_t)(((((kt * 4 + ks2) * 2 + bh) * 32 + gid * 4 + tig) * 16)
                                     + (q & 1) * 8);

    float Uv[4][2], Bv[4][2];
    #pragma unroll
    for (int g = 0; g < 4; ++g) {
        Uv[g][0] = p.U[g][i * N_DIM + kg0];     Uv[g][1] = p.U[g][i * N_DIM + kg0 + 1];
        Bv[g][0] = p.bias[g][i * N_DIM + kg0];  Bv[g][1] = p.bias[g][i * N_DIM + kg0 + 1];
    }
    float creg[4] = {0.f, 0.f, 0.f, 0.f};
    float hreg[4] = {0.f, 0.f, 0.f, 0.f};
    float xc0 = __ldg(&p.x[((size_t)b0 * T_STEPS) * I_CH + i]);
    float xc1 = __ldg(&p.x[((size_t)(b0 + 8) * T_STEPS) * I_CH + i]);

    // prime 4-deep B pipeline (it = 0..3); wrap-around keeps it full across steps
    uint4 Bp[4][2];
    #pragma unroll
    for (int s = 0; s < 4; ++s) {
        const uint8_t* qp = wq + (s & 3) * 8192;   // c=0
        Bp[s][0] = __ldg(reinterpret_cast<const uint4*>(qp));
        Bp[s][1] = __ldg(reinterpret_cast<const uint4*>(qp + 512));
    }

    for (int t = 0; t < T_STEPS; ++t) {
        // ---- stage A: raw linear copy of producer-packed fragments (64KB) ----
        {
            const uint4* src = reinterpret_cast<const uint4*>(hf_ch);
            uint4* dst = reinterpret_cast<uint4*>(sm);
            #pragma unroll
            for (int o = 0; o < 8; ++o) {
                dst[o * 512 + tid] = __ldcg(&src[o * 512 + tid]);
            }
        }
        __syncthreads();

        // ---- mainloop: 32 flat (c,ks) iterations, 4-deep wrap-around B pipeline ----
        float d[4][4];
        #pragma unroll
        for (int a = 0; a < 4; ++a)
            #pragma unroll
            for (int b = 0; b < 4; ++b) d[a][b] = 0.0f;

        #pragma unroll
        for (int it = 0; it < 32; ++it) {
            const int sl = it & 3;
            uint4 U0 = Bp[sl][0], U1 = Bp[sl][1];
            {
                const int it2 = (it + 4) & 31;    // wraps to next step's head at tail
                const uint8_t* qp = wq + (it2 >> 2) * 32768 + (it2 & 3) * 8192;
                Bp[sl][0] = __ldg(reinterpret_cast<const uint4*>(qp));
                Bp[sl][1] = __ldg(reinterpret_cast<const uint4*>(qp + 512));
            }
            uint32_t ab = (uint32_t)(((it * 2 + bh) * 32 + lane) * 16);
            uint4 Ah = *reinterpret_cast<const uint4*>(sm + ab);
            uint4 Al = *reinterpret_cast<const uint4*>(sm + SM_A_LO + ab);
            mma16816(d[0], Ah.x, Ah.y, Ah.z, Ah.w, U0.x, U0.y);
            mma16816(d[0], Al.x, Al.y, Al.z, Al.w, U0.x, U0.y);
            mma16816(d[1], Ah.x, Ah.y, Ah.z, Ah.w, U0.z, U0.w);
            mma16816(d[1], Al.x, Al.y, Al.z, Al.w, U0.z, U0.w);
            mma16816(d[2], Ah.x, Ah.y, Ah.z, Ah.w, U1.x, U1.y);
            mma16816(d[2], Al.x, Al.y, Al.z, Al.w, U1.x, U1.y);
            mma16816(d[3], Ah.x, Ah.y, Ah.z, Ah.w, U1.z, U1.w);
            mma16816(d[3], Al.x, Al.y, Al.z, Al.w, U1.z, U1.w);
        }

        // prefetch next-step x (pre-barrier, independent)
        float xn0 = 0.f, xn1 = 0.f;
        if (t + 1 < T_STEPS) {
            xn0 = __ldg(&p.x[((size_t)b0 * T_STEPS + t + 1) * I_CH + i]);
            xn1 = __ldg(&p.x[((size_t)(b0 + 8) * T_STEPS + t + 1) * I_CH + i]);
        }

        // ---- register-resident pointwise epilogue ----
        const float DT = 0.01f;
        const float A_OUT = 0.9900498337491681f;
        const float OMA_OUT = 0.009950166250831947f;
        #pragma unroll
        for (int rb = 0; rb < 2; ++rb) {
            int b = b0 + rb * 8;
            float xb = rb ? xc1 : xc0;
            float2 hv;
            #pragma unroll
            for (int rc = 0; rc < 2; ++rc) {
                int e = rb * 2 + rc;
                float pj = d[0][e] + xb * Uv[0][rc] + Bv[0][rc];
                float pi = d[1][e] + xb * Uv[1][rc] + Bv[1][rc];
                float pf = d[2][e] + xb * Uv[2][rc] + Bv[2][rc];
                float po = d[3][e] + xb * Uv[3][rc] + Bv[3][rc];

                float j  = tanhf(pj);
                float ig = 1.0f / (1.0f + expf(-pi));
                float fg = 1.0f / (1.0f + expf(-pf));
                float og = 1.0f / (1.0f + expf(-po));

                float h_old = hreg[e];
                float xm = -7.8125e-5f * j;
                float alpha_m = 1.0f + xm + 0.5f * xm * xm;
                float xr = -1.5625e-4f * ig;
                float ro = 1.0f + xr + 0.5f * xr * xr;
                float b_ad = ro * 0.1f + (1.0f - ro) * ig;
                float Bth  = 0.04f + 1.8f * b_ad;
                float mem  = j * alpha_m + (1.0f - alpha_m) * h_old - Bth * ig * DT;
                float spike = (mem - Bth) > 0.0f ? 1.0f : 0.0f;
                float mem_out = mem * A_OUT + OMA_OUT * spike + 0.08f;

                float c_new = creg[e] * fg + ig * spike * mem_out;
                creg[e] = c_new;
                float h_new = og * tanhf(c_new);
                hreg[e] = h_new;
                if (rc == 0) hv.x = h_new; else hv.y = h_new;
            }
            *reinterpret_cast<float2*>(
                p.out + (((size_t)b * T_STEPS + t) * I_CH + i) * N_DIM + kg0) = hv;
            if (t == T_STEPS - 1) {
                float* h_fin = p.out + (size_t)B_SZ * T_STEPS * I_CH * N_DIM;
                float* c_fin = h_fin + B_SZ * I_CH * N_DIM;
                size_t fidx = ((size_t)b * I_CH + i) * N_DIM + kg0;
                *reinterpret_cast<float2*>(h_fin + fidx) = hv;
                *reinterpret_cast<float2*>(c_fin + fidx) =
                    make_float2(creg[rb * 2], creg[rb * 2 + 1]);
            }
        }
        xc0 = xn0; xc1 = xn1;

        // ---- producer-side fragment packing for next step ----
        if (t + 1 < T_STEPS) {
            __half h00 = __float2half_rn(hreg[0]), h01 = __float2half_rn(hreg[1]);
            __half h20 = __float2half_rn(hreg[2]), h21 = __float2half_rn(hreg[3]);
            uint32_t hv0 = (uint32_t)__half_as_ushort(h00) |
                           ((uint32_t)__half_as_ushort(h01) << 16);
            uint32_t hv8 = (uint32_t)__half_as_ushort(h20) |
                           ((uint32_t)__half_as_ushort(h21) << 16);
            uint32_t lv0 = packh(hreg[0] - __half2float(h00), hreg[1] - __half2float(h01));
            uint32_t lv8 = packh(hreg[2] - __half2float(h20), hreg[3] - __half2float(h21));
            __stcg(reinterpret_cast<uint2*>(hf_ch + a16b),         make_uint2(hv0, hv8));
            __stcg(reinterpret_cast<uint2*>(hf_ch + 32768 + a16b), make_uint2(lv0, lv8));
        }

        // ---- grid barrier (128 CTAs, all co-resident) ----
        if (t + 1 < T_STEPS) {
            __threadfence();
            __syncthreads();
            if (tid == 0) {
                atomicAdd(&g_bar, 1u);
                unsigned target = (unsigned)(t + 1) * 128u;
                unsigned v;
                do {
                    asm volatile("ld.acquire.gpu.u32 %0, [%1];"
                                 : "=r"(v) : "l"(&g_bar) : "memory");
                } while (v < target);
            }
            __syncthreads();
        }
    }
}

extern "C" void kernel_launch(void* const* d_in, const int* in_sizes, int n_in,
                              void* d_out, int out_size) {
    Params p;
    p.x = (const float*)d_in[0];
    for (int g = 0; g < 4; ++g) {
        p.U[g]    = (const float*)d_in[1 + g];
        p.W[g]    = (const float*)d_in[5 + g];
        p.bias[g] = (const float*)d_in[9 + g];
    }
    p.out = (float*)d_out;

    cudaFuncSetAttribute(persist_kernel, cudaFuncAttributeMaxDynamicSharedMemorySize, SM_TOT);

    prep_kernel<<<128, 256>>>(p);                 // packs W, zeroes h-frag, resets g_bar
    dim3 grid(8, I_CH);                           // 128 blocks, all co-resident
    persist_kernel<<<grid, 512, SM_TOT>>>(p);
}